// round 4
// baseline (speedup 1.0000x reference)
#include <cuda_runtime.h>

#define L_   9
#define C_   256
#define K_   3
#define V_   25
#define VP_  32
#define G_   9
#define T_   128
#define NC_  60
#define CIN_ 3
#define GH_  4
#define CV_  (C_*V_)    /* 6400 */
#define CVP_ (C_*VP_)   /* 8192 */

typedef unsigned long long ull;

__device__ __forceinline__ ull ffma2(ull a, ull b, ull c) {
    ull d; asm("fma.rn.f32x2 %0, %1, %2, %3;" : "=l"(d) : "l"(a), "l"(b), "l"(c)); return d;
}
__device__ __forceinline__ ull pack2(float x, float y) {
    ull d; asm("mov.b64 %0, {%1, %2};" : "=l"(d) : "f"(x), "f"(y)); return d;
}
__device__ __forceinline__ float2 unpack2(ull a) {
    float2 r; asm("mov.b64 {%0, %1}, %2;" : "=f"(r.x), "=f"(r.y) : "l"(a)); return r;
}

// ---------------- scratch (device globals) ----------------------------------
__device__ __align__(16) float g_h[2][T_][CVP_];      // padded activations
__device__ __align__(16) float g_anorm[T_][CVP_];     // relu(LN1(z)), padded
__device__ __align__(16) float g_aneg[L_][CVP_];      // relu(LN1(zero frame)) per layer
__device__ __align__(16) float2 g_Wg2[L_][K_][C_][C_];// dup pairs [l][k][ci][co]
__device__ __align__(16) float2 g_Wt2[L_][G_][C_][C_];// dup pairs [l][g][ci][o]

// ---------------- weight prep (transpose + duplicate) ------------------------
__global__ void k_prep_wg(const float* __restrict__ Wg) {
    int idx = blockIdx.x * blockDim.x + threadIdx.x;
    if (idx >= L_ * K_ * C_ * C_) return;
    int ci = idx % C_; int r = idx / C_;
    int co = r % C_;   r /= C_;
    int k  = r % K_;   int l = r / K_;
    float w = Wg[((size_t)(l * K_ * C_ + k * C_ + co)) * C_ + ci];  // coalesced read
    g_Wg2[l][k][ci][co] = make_float2(w, w);
}

__global__ void k_prep_wt(const float* __restrict__ Wt) {
    int idx = blockIdx.x * blockDim.x + threadIdx.x;
    if (idx >= L_ * C_ * C_) return;
    int c = idx % C_; int r = idx / C_;
    int o = r % C_;   int l = r / C_;
    const float* src = Wt + (((size_t)(l * C_ + o)) * C_ + c) * G_;  // 9 consecutive
    #pragma unroll
    for (int g = 0; g < G_; g++) {
        float w = src[g];
        g_Wt2[l][g][c][o] = make_float2(w, w);
    }
}

__global__ void k_prep_aneg(const float* __restrict__ ln1_b) {
    int idx = blockIdx.x * blockDim.x + threadIdx.x;
    if (idx >= L_ * CVP_) return;
    int e = idx % CVP_, l = idx / CVP_;
    int c = e >> 5, v = e & 31;
    float r = 0.f;
    if (v < V_) r = fmaxf(ln1_b[(l * C_ + c) * V_ + v], 0.f);
    g_aneg[l][e] = r;
}

// ---------------- input: LN over (CIN,V) + 1x1 conv --------------------------
__global__ void k_input(const float* __restrict__ x,
                        const float* __restrict__ lnw,
                        const float* __restrict__ lnb,
                        const float* __restrict__ Win,
                        const float* __restrict__ bin) {
    __shared__ float hn[CIN_ * V_];
    __shared__ float red[16];
    int t = blockIdx.x, tid = threadIdx.x;  // 128 threads

    float xv = 0.f, s = 0.f, ss = 0.f;
    if (tid < CIN_ * V_) {
        int ci = tid / V_, v = tid % V_;
        xv = x[(size_t)ci * T_ * V_ + (size_t)t * V_ + v];
        s = xv; ss = xv * xv;
    }
    #pragma unroll
    for (int o = 16; o; o >>= 1) {
        s  += __shfl_xor_sync(0xffffffffu, s, o);
        ss += __shfl_xor_sync(0xffffffffu, ss, o);
    }
    int wid = tid >> 5, lane = tid & 31;
    if (lane == 0) { red[wid] = s; red[4 + wid] = ss; }
    __syncthreads();
    if (tid == 0) {
        float S = red[0] + red[1] + red[2] + red[3];
        float SS = red[4] + red[5] + red[6] + red[7];
        float m = S / (CIN_ * V_);
        red[8] = m;
        red[9] = rsqrtf(SS / (CIN_ * V_) - m * m + 1e-5f);
    }
    __syncthreads();
    float m = red[8], rs = red[9];
    if (tid < CIN_ * V_) hn[tid] = (xv - m) * rs * lnw[tid] + lnb[tid];
    __syncthreads();

    float* out = g_h[0][t];
    for (int e = tid; e < CVP_; e += 128) {
        int c = e >> 5, v = e & 31;
        float a = 0.f;
        if (v < V_) {
            a = bin[c];
            #pragma unroll
            for (int ci = 0; ci < CIN_; ci++)
                a = fmaf(Win[c * CIN_ + ci], hn[ci * V_ + v], a);
        }
        out[e] = a;
    }
}

// ---------------- GCN: z = sum_k (Wg_k h) A_k + LN1 + relu -------------------
#define GCN_SMEM_FLOATS (CVP_ + K_*CVP_ + K_*V_*V_ + K_*V_ + 66)
__global__ __launch_bounds__(1024, 1)
void k_gcn(int l, int cur,
           const float* __restrict__ A,
           const float* __restrict__ imp,
           const float* __restrict__ bg,
           const float* __restrict__ ln1_w,
           const float* __restrict__ ln1_b) {
    extern __shared__ __align__(16) float sm[];
    float* h_s  = sm;                          // 8192
    float* hA_s = sm + CVP_;                   // 24576: [k][c][wp32]
    float* Al_s = sm + CVP_ + K_*CVP_;         // 1875
    float* rsum = Al_s + K_*V_*V_;             // 75
    float* red  = rsum + K_*V_;                // 66

    int t = blockIdx.x, tid = threadIdx.x;     // 1024 threads
    {
        const float4* src = (const float4*)g_h[cur][t];
        float4* dst = (float4*)h_s;
        #pragma unroll
        for (int i = 0; i < 2; i++) dst[tid + i * 1024] = src[tid + i * 1024];
    }
    for (int i = tid; i < K_ * V_ * V_; i += 1024)
        Al_s[i] = A[i] * imp[l * K_ * V_ * V_ + i];
    __syncthreads();

    for (int i = tid; i < K_ * V_; i += 1024) {
        int k = i / V_, w = i % V_;
        float s = 0.f;
        #pragma unroll
        for (int v = 0; v < V_; v++) s += Al_s[k * V_ * V_ + v * V_ + w];
        rsum[i] = s;
    }
    // hA[k][c][w] = sum_v h[c][v] * Al[k][v][w]   (padded stride 32)
    for (int e = tid; e < K_ * CV_; e += 1024) {
        int k = e / CV_, r = e % CV_, c = r / V_, w = r % V_;
        const float* hr = h_s + (c << 5);
        const float* ar = Al_s + k * V_ * V_ + w;
        float s = 0.f;
        #pragma unroll
        for (int v = 0; v < V_; v++) s = fmaf(hr[v], ar[v * V_], s);
        hA_s[k * CVP_ + (c << 5) + w] = s;
    }
    // zero the pad columns
    for (int e = tid; e < K_ * C_; e += 1024) {
        float* p = hA_s + (e >> 8) * CVP_ + ((e & 255) << 5);
        #pragma unroll
        for (int w = V_; w < VP_; w++) p[w] = 0.f;
    }
    __syncthreads();

    int c = tid & 255, vg = tid >> 8, vb = vg << 3;
    ull acc[4];
    {
        float b0 = bg[l * K_ * C_ + c];
        float b1 = bg[l * K_ * C_ + C_ + c];
        float b2 = bg[l * K_ * C_ + 2 * C_ + c];
        float tmp[8];
        #pragma unroll
        for (int j = 0; j < 8; j++) {
            int w = vb + j;
            tmp[j] = (w < V_) ? b0 * rsum[w] + b1 * rsum[V_ + w] + b2 * rsum[2 * V_ + w]
                              : 0.f;
        }
        #pragma unroll
        for (int j = 0; j < 4; j++) acc[j] = pack2(tmp[2 * j], tmp[2 * j + 1]);
    }
    #pragma unroll
    for (int k = 0; k < K_; k++) {
        const float2* wg = g_Wg2[l][k][0] + c;
        const float* ap = hA_s + k * CVP_ + vb;
        #pragma unroll 2
        for (int ci = 0; ci < C_; ci++) {
            ull wv = *reinterpret_cast<const ull*>(wg + ci * C_);
            const ulonglong2* hp = reinterpret_cast<const ulonglong2*>(ap + (ci << 5));
            ulonglong2 h01 = hp[0], h23 = hp[1];
            acc[0] = ffma2(wv, h01.x, acc[0]);
            acc[1] = ffma2(wv, h01.y, acc[1]);
            acc[2] = ffma2(wv, h23.x, acc[2]);
            acc[3] = ffma2(wv, h23.y, acc[3]);
        }
    }

    float o8[8];
    #pragma unroll
    for (int j = 0; j < 4; j++) { float2 a = unpack2(acc[j]); o8[2*j] = a.x; o8[2*j+1] = a.y; }
    float s = 0.f, ss = 0.f;
    #pragma unroll
    for (int j = 0; j < 8; j++)
        if (vb + j < V_) { s += o8[j]; ss += o8[j] * o8[j]; }
    #pragma unroll
    for (int o = 16; o; o >>= 1) {
        s  += __shfl_xor_sync(0xffffffffu, s, o);
        ss += __shfl_xor_sync(0xffffffffu, ss, o);
    }
    int wid = tid >> 5, lane = tid & 31;
    if (lane == 0) { red[wid] = s; red[32 + wid] = ss; }
    __syncthreads();
    if (tid < 32) {
        float S = red[tid], SS = red[32 + tid];
        #pragma unroll
        for (int o = 16; o; o >>= 1) {
            S  += __shfl_xor_sync(0xffffffffu, S, o);
            SS += __shfl_xor_sync(0xffffffffu, SS, o);
        }
        if (tid == 0) {
            float m = S / CV_;
            red[64] = m;
            red[65] = rsqrtf(SS / CV_ - m * m + 1e-5f);
        }
    }
    __syncthreads();
    float m = red[64], rs = red[65];

    float* outp = g_anorm[t] + (c << 5) + vb;
    const float* w1 = ln1_w + (l * C_ + c) * V_ + vb;
    const float* b1 = ln1_b + (l * C_ + c) * V_ + vb;
    #pragma unroll
    for (int j = 0; j < 8; j++) {
        float r = 0.f;
        if (vb + j < V_)
            r = fmaxf(fmaf((o8[j] - m) * rs, w1[j], b1[j]), 0.f);
        outp[j] = r;
    }
}

// ---------------- TCN: temporal conv + LN2 + residual + relu -----------------
__global__ __launch_bounds__(1024, 1)
void k_tcn(int l, int cur,
           const float* __restrict__ bt,
           const float* __restrict__ ln2_w,
           const float* __restrict__ ln2_b) {
    __shared__ __align__(16) float a_s[CVP_];
    __shared__ float red[66];
    int t = blockIdx.x, tid = threadIdx.x;     // 1024 threads
    int o = tid & 255, vg = tid >> 8, vb = vg << 3;

    ull acc[4];
    {
        float btv = bt[l * C_ + o];
        ull b2v = pack2(btv, btv);
        acc[0] = b2v; acc[1] = b2v; acc[2] = b2v; acc[3] = b2v;
    }

    for (int g = 0; g < G_; g++) {
        __syncthreads();
        int tau = t - g;
        const float4* src = (const float4*)((tau >= 0) ? g_anorm[tau] : g_aneg[l]);
        float4* dst = (float4*)a_s;
        #pragma unroll
        for (int i = 0; i < 2; i++) dst[tid + i * 1024] = src[tid + i * 1024];
        __syncthreads();

        const float2* wt = g_Wt2[l][g][0] + o;
        const float* ap = a_s + vb;
        #pragma unroll 2
        for (int ci = 0; ci < C_; ci++) {
            ull wv = *reinterpret_cast<const ull*>(wt + ci * C_);
            const ulonglong2* hp = reinterpret_cast<const ulonglong2*>(ap + (ci << 5));
            ulonglong2 h01 = hp[0], h23 = hp[1];
            acc[0] = ffma2(wv, h01.x, acc[0]);
            acc[1] = ffma2(wv, h01.y, acc[1]);
            acc[2] = ffma2(wv, h23.x, acc[2]);
            acc[3] = ffma2(wv, h23.y, acc[3]);
        }
    }

    float o8[8];
    #pragma unroll
    for (int j = 0; j < 4; j++) { float2 a = unpack2(acc[j]); o8[2*j] = a.x; o8[2*j+1] = a.y; }
    float s = 0.f, ss = 0.f;
    #pragma unroll
    for (int j = 0; j < 8; j++)
        if (vb + j < V_) { s += o8[j]; ss += o8[j] * o8[j]; }
    #pragma unroll
    for (int off = 16; off; off >>= 1) {
        s  += __shfl_xor_sync(0xffffffffu, s, off);
        ss += __shfl_xor_sync(0xffffffffu, ss, off);
    }
    int wid = tid >> 5, lane = tid & 31;
    if (lane == 0) { red[wid] = s; red[32 + wid] = ss; }
    __syncthreads();
    if (tid < 32) {
        float S = red[tid], SS = red[32 + tid];
        #pragma unroll
        for (int off = 16; off; off >>= 1) {
            S  += __shfl_xor_sync(0xffffffffu, S, off);
            SS += __shfl_xor_sync(0xffffffffu, SS, off);
        }
        if (tid == 0) {
            float m = S / CV_;
            red[64] = m;
            red[65] = rsqrtf(SS / CV_ - m * m + 1e-5f);
        }
    }
    __syncthreads();
    float m = red[64], rs = red[65];

    const float* resp = (t >= GH_) ? (g_h[cur][t - GH_] + (o << 5) + vb) : nullptr;
    float* outp = g_h[cur ^ 1][t] + (o << 5) + vb;
    const float* w2 = ln2_w + (l * C_ + o) * V_ + vb;
    const float* b2 = ln2_b + (l * C_ + o) * V_ + vb;
    #pragma unroll
    for (int j = 0; j < 8; j++) {
        float r = 0.f;
        if (vb + j < V_) {
            float res = resp ? resp[j] : 0.f;
            r = fmaxf(fmaf((o8[j] - m) * rs, w2[j], b2[j]) + res, 0.f);
        }
        outp[j] = r;
    }
}

// ---------------- head: mean over V + linear ---------------------------------
__global__ void k_out(int cur,
                      const float* __restrict__ Wout,
                      const float* __restrict__ bout,
                      float* __restrict__ out) {
    __shared__ float pooled[C_];
    int t = blockIdx.x, tid = threadIdx.x;  // 256
    const float* h = g_h[cur][t];
    float s = 0.f;
    #pragma unroll
    for (int v = 0; v < V_; v++) s += h[(tid << 5) + v];
    pooled[tid] = s * (1.f / V_);
    __syncthreads();
    if (tid < NC_) {
        float a = bout[tid];
        #pragma unroll 8
        for (int c = 0; c < C_; c++) a = fmaf(Wout[tid * C_ + c], pooled[c], a);
        out[t * NC_ + tid] = a;
    }
}

// ---------------- launch ------------------------------------------------------
extern "C" void kernel_launch(void* const* d_in, const int* in_sizes, int n_in,
                              void* d_out, int out_size) {
    const float* x       = (const float*)d_in[0];
    const float* A       = (const float*)d_in[1];
    const float* ln_in_w = (const float*)d_in[2];
    const float* ln_in_b = (const float*)d_in[3];
    const float* W_in    = (const float*)d_in[4];
    const float* b_in    = (const float*)d_in[5];
    const float* Wg      = (const float*)d_in[6];
    const float* bg      = (const float*)d_in[7];
    const float* ln1_w   = (const float*)d_in[8];
    const float* ln1_b   = (const float*)d_in[9];
    const float* Wt      = (const float*)d_in[10];
    const float* bt      = (const float*)d_in[11];
    const float* ln2_w   = (const float*)d_in[12];
    const float* ln2_b   = (const float*)d_in[13];
    const float* imp     = (const float*)d_in[14];
    const float* W_out   = (const float*)d_in[15];
    const float* b_out   = (const float*)d_in[16];
    float* out = (float*)d_out;

    int gcn_smem = GCN_SMEM_FLOATS * (int)sizeof(float);
    cudaFuncSetAttribute(k_gcn, cudaFuncAttributeMaxDynamicSharedMemorySize, gcn_smem);

    {
        int n = L_ * K_ * C_ * C_;
        k_prep_wg<<<(n + 255) / 256, 256>>>(Wg);
    }
    {
        int n = L_ * C_ * C_;
        k_prep_wt<<<(n + 255) / 256, 256>>>(Wt);
    }
    {
        int n = L_ * CVP_;
        k_prep_aneg<<<(n + 255) / 256, 256>>>(ln1_b);
    }
    k_input<<<T_, 128>>>(x, ln_in_w, ln_in_b, W_in, b_in);

    int cur = 0;
    for (int l = 0; l < L_; l++) {
        k_gcn<<<T_, 1024, gcn_smem>>>(l, cur, A, imp, bg, ln1_w, ln1_b);
        k_tcn<<<T_, 1024>>>(l, cur, bt, ln2_w, ln2_b);
        cur ^= 1;
    }
    k_out<<<T_, 256>>>(cur, W_out, b_out, out);
}

// round 8
// speedup vs baseline: 1.6998x; 1.6998x over previous
#include <cuda_runtime.h>

#define L_   9
#define C_   256
#define K_   3
#define V_   25
#define VP_  32
#define G_   9
#define T_   128
#define NC_  60
#define CIN_ 3
#define GH_  4
#define CV_  (C_*V_)    /* 6400 */
#define CVP_ (C_*VP_)   /* 8192 */

// ---------------- scratch (device globals) ----------------------------------
__device__ __align__(16) float g_h[2][T_][CVP_];      // padded activations
__device__ __align__(16) float g_anorm[T_][CVP_];     // relu(LN1(z)), padded
__device__ __align__(16) float g_aneg[L_][CVP_];      // relu(LN1(zero frame)) per layer
__device__ __align__(16) float g_WgT[L_][K_][C_][C_]; // [l][k][ci][co]
__device__ __align__(16) float g_WtT[L_][G_][C_][C_]; // [l][g][ci][o]

// ---------------- weight prep (transpose) ------------------------------------
__global__ void k_prep_wg(const float* __restrict__ Wg) {
    int idx = blockIdx.x * blockDim.x + threadIdx.x;
    if (idx >= L_ * K_ * C_ * C_) return;
    int ci = idx % C_; int r = idx / C_;
    int co = r % C_;   r /= C_;
    int k  = r % K_;   int l = r / K_;
    g_WgT[l][k][ci][co] = Wg[((size_t)(l * K_ * C_ + k * C_ + co)) * C_ + ci];
}

__global__ void k_prep_wt(const float* __restrict__ Wt) {
    int idx = blockIdx.x * blockDim.x + threadIdx.x;
    if (idx >= L_ * C_ * C_) return;
    int c = idx % C_; int r = idx / C_;
    int o = r % C_;   int l = r / C_;
    const float* src = Wt + (((size_t)(l * C_ + o)) * C_ + c) * G_;  // 9 consecutive
    #pragma unroll
    for (int g = 0; g < G_; g++) g_WtT[l][g][c][o] = src[g];
}

__global__ void k_prep_aneg(const float* __restrict__ ln1_b) {
    int idx = blockIdx.x * blockDim.x + threadIdx.x;
    if (idx >= L_ * CVP_) return;
    int e = idx % CVP_, l = idx / CVP_;
    int c = e >> 5, v = e & 31;
    float r = 0.f;
    if (v < V_) r = fmaxf(ln1_b[(l * C_ + c) * V_ + v], 0.f);
    g_aneg[l][e] = r;
}

// ---------------- input: LN over (CIN,V) + 1x1 conv --------------------------
__global__ void k_input(const float* __restrict__ x,
                        const float* __restrict__ lnw,
                        const float* __restrict__ lnb,
                        const float* __restrict__ Win,
                        const float* __restrict__ bin) {
    __shared__ float hn[CIN_ * V_];
    __shared__ float red[16];
    int t = blockIdx.x, tid = threadIdx.x;  // 128 threads

    float xv = 0.f, s = 0.f, ss = 0.f;
    if (tid < CIN_ * V_) {
        int ci = tid / V_, v = tid % V_;
        xv = x[(size_t)ci * T_ * V_ + (size_t)t * V_ + v];
        s = xv; ss = xv * xv;
    }
    #pragma unroll
    for (int o = 16; o; o >>= 1) {
        s  += __shfl_xor_sync(0xffffffffu, s, o);
        ss += __shfl_xor_sync(0xffffffffu, ss, o);
    }
    int wid = tid >> 5, lane = tid & 31;
    if (lane == 0) { red[wid] = s; red[4 + wid] = ss; }
    __syncthreads();
    if (tid == 0) {
        float S = red[0] + red[1] + red[2] + red[3];
        float SS = red[4] + red[5] + red[6] + red[7];
        float m = S / (CIN_ * V_);
        red[8] = m;
        red[9] = rsqrtf(SS / (CIN_ * V_) - m * m + 1e-5f);
    }
    __syncthreads();
    float m = red[8], rs = red[9];
    if (tid < CIN_ * V_) hn[tid] = (xv - m) * rs * lnw[tid] + lnb[tid];
    __syncthreads();

    float* out = g_h[0][t];
    for (int e = tid; e < CVP_; e += 128) {
        int c = e >> 5, v = e & 31;
        float a = 0.f;
        if (v < V_) {
            a = bin[c];
            #pragma unroll
            for (int ci = 0; ci < CIN_; ci++)
                a = fmaf(Win[c * CIN_ + ci], hn[ci * V_ + v], a);
        }
        out[e] = a;
    }
}

// ---------------- GCN: z = sum_k (Wg_k h) A_k + LN1 + relu -------------------
#define GCN_SMEM_FLOATS (CVP_ + K_*CVP_ + K_*V_*V_ + K_*V_ + 66)
__global__ __launch_bounds__(1024, 1)
void k_gcn(int l, int cur,
           const float* __restrict__ A,
           const float* __restrict__ imp,
           const float* __restrict__ bg,
           const float* __restrict__ ln1_w,
           const float* __restrict__ ln1_b) {
    extern __shared__ __align__(16) float sm[];
    float* h_s  = sm;                          // 8192 (stride-32 padded)
    float* hA_s = sm + CVP_;                   // 24576: [k][c][wp32]
    float* Al_s = sm + CVP_ + K_*CVP_;         // 1875
    float* rsum = Al_s + K_*V_*V_;             // 75
    float* red  = rsum + K_*V_;                // 66

    int t = blockIdx.x, tid = threadIdx.x;     // 1024 threads
    {
        const float4* src = (const float4*)g_h[cur][t];
        float4* dst = (float4*)h_s;
        #pragma unroll
        for (int i = 0; i < 2; i++) dst[tid + i * 1024] = src[tid + i * 1024];
    }
    for (int i = tid; i < K_ * V_ * V_; i += 1024)
        Al_s[i] = A[i] * imp[l * K_ * V_ * V_ + i];
    __syncthreads();

    for (int i = tid; i < K_ * V_; i += 1024) {
        int k = i / V_, w = i % V_;
        float s = 0.f;
        #pragma unroll
        for (int v = 0; v < V_; v++) s += Al_s[k * V_ * V_ + v * V_ + w];
        rsum[i] = s;
    }
    // hA[k][c][w] = sum_v h[c][v] * Al[k][v][w]   (padded stride 32)
    for (int e = tid; e < K_ * CV_; e += 1024) {
        int k = e / CV_, r = e % CV_, c = r / V_, w = r % V_;
        const float* hr = h_s + (c << 5);
        const float* ar = Al_s + k * V_ * V_ + w;
        float s = 0.f;
        #pragma unroll
        for (int v = 0; v < V_; v++) s = fmaf(hr[v], ar[v * V_], s);
        hA_s[k * CVP_ + (c << 5) + w] = s;
    }
    // zero pad columns
    for (int e = tid; e < K_ * C_; e += 1024) {
        float* p = hA_s + (e >> 8) * CVP_ + ((e & 255) << 5);
        #pragma unroll
        for (int w = V_; w < VP_; w++) p[w] = 0.f;
    }
    __syncthreads();

    int c = tid & 255, vg = tid >> 8, vb = vg << 3;
    float acc[8];
    {
        float b0 = bg[l * K_ * C_ + c];
        float b1 = bg[l * K_ * C_ + C_ + c];
        float b2 = bg[l * K_ * C_ + 2 * C_ + c];
        #pragma unroll
        for (int j = 0; j < 8; j++) {
            int w = vb + j;
            acc[j] = (w < V_) ? b0 * rsum[w] + b1 * rsum[V_ + w] + b2 * rsum[2 * V_ + w]
                              : 0.f;
        }
    }
    #pragma unroll
    for (int k = 0; k < K_; k++) {
        const float* wg = &g_WgT[l][k][0][c];
        const float* ap = hA_s + k * CVP_ + vb;
        #pragma unroll 4
        for (int ci = 0; ci < C_; ci++) {
            float wv = wg[ci * C_];
            float4 h0 = *(const float4*)(ap + (ci << 5));
            float4 h1 = *(const float4*)(ap + (ci << 5) + 4);
            acc[0] = fmaf(wv, h0.x, acc[0]);
            acc[1] = fmaf(wv, h0.y, acc[1]);
            acc[2] = fmaf(wv, h0.z, acc[2]);
            acc[3] = fmaf(wv, h0.w, acc[3]);
            acc[4] = fmaf(wv, h1.x, acc[4]);
            acc[5] = fmaf(wv, h1.y, acc[5]);
            acc[6] = fmaf(wv, h1.z, acc[6]);
            acc[7] = fmaf(wv, h1.w, acc[7]);
        }
    }

    // LN1 stats over (C,V)
    float s = 0.f, ss = 0.f;
    #pragma unroll
    for (int j = 0; j < 8; j++)
        if (vb + j < V_) { s += acc[j]; ss += acc[j] * acc[j]; }
    #pragma unroll
    for (int o = 16; o; o >>= 1) {
        s  += __shfl_xor_sync(0xffffffffu, s, o);
        ss += __shfl_xor_sync(0xffffffffu, ss, o);
    }
    int wid = tid >> 5, lane = tid & 31;
    if (lane == 0) { red[wid] = s; red[32 + wid] = ss; }
    __syncthreads();
    if (tid < 32) {
        float S = red[tid], SS = red[32 + tid];
        #pragma unroll
        for (int o = 16; o; o >>= 1) {
            S  += __shfl_xor_sync(0xffffffffu, S, o);
            SS += __shfl_xor_sync(0xffffffffu, SS, o);
        }
        if (tid == 0) {
            float m = S / CV_;
            red[64] = m;
            red[65] = rsqrtf(SS / CV_ - m * m + 1e-5f);
        }
    }
    __syncthreads();
    float m = red[64], rs = red[65];

    float* outp = g_anorm[t] + (c << 5) + vb;
    const float* w1 = ln1_w + (l * C_ + c) * V_ + vb;
    const float* b1 = ln1_b + (l * C_ + c) * V_ + vb;
    #pragma unroll
    for (int j = 0; j < 8; j++) {
        float r = 0.f;
        if (vb + j < V_)
            r = fmaxf(fmaf((acc[j] - m) * rs, w1[j], b1[j]), 0.f);
        outp[j] = r;
    }
}

// ---------------- TCN: temporal conv + LN2 + residual + relu -----------------
__global__ __launch_bounds__(1024, 1)
void k_tcn(int l, int cur,
           const float* __restrict__ bt,
           const float* __restrict__ ln2_w,
           const float* __restrict__ ln2_b) {
    __shared__ __align__(16) float a_s[CVP_];
    __shared__ float red[66];
    int t = blockIdx.x, tid = threadIdx.x;     // 1024 threads
    int o = tid & 255, vg = tid >> 8, vb = vg << 3;

    float acc[8];
    {
        float btv = bt[l * C_ + o];
        #pragma unroll
        for (int j = 0; j < 8; j++) acc[j] = btv;
    }

    for (int g = 0; g < G_; g++) {
        __syncthreads();
        int tau = t - g;
        const float4* src = (const float4*)((tau >= 0) ? g_anorm[tau] : g_aneg[l]);
        float4* dst = (float4*)a_s;
        #pragma unroll
        for (int i = 0; i < 2; i++) dst[tid + i * 1024] = src[tid + i * 1024];
        __syncthreads();

        const float* wt = &g_WtT[l][g][0][o];
        const float* ap = a_s + vb;
        #pragma unroll 4
        for (int ci = 0; ci < C_; ci++) {
            float wv = wt[ci * C_];
            float4 a0 = *(const float4*)(ap + (ci << 5));
            float4 a1 = *(const float4*)(ap + (ci << 5) + 4);
            acc[0] = fmaf(wv, a0.x, acc[0]);
            acc[1] = fmaf(wv, a0.y, acc[1]);
            acc[2] = fmaf(wv, a0.z, acc[2]);
            acc[3] = fmaf(wv, a0.w, acc[3]);
            acc[4] = fmaf(wv, a1.x, acc[4]);
            acc[5] = fmaf(wv, a1.y, acc[5]);
            acc[6] = fmaf(wv, a1.z, acc[6]);
            acc[7] = fmaf(wv, a1.w, acc[7]);
        }
    }

    // LN2 stats over (C,V)
    float s = 0.f, ss = 0.f;
    #pragma unroll
    for (int j = 0; j < 8; j++)
        if (vb + j < V_) { s += acc[j]; ss += acc[j] * acc[j]; }
    #pragma unroll
    for (int off = 16; off; off >>= 1) {
        s  += __shfl_xor_sync(0xffffffffu, s, off);
        ss += __shfl_xor_sync(0xffffffffu, ss, off);
    }
    int wid = tid >> 5, lane = tid & 31;
    if (lane == 0) { red[wid] = s; red[32 + wid] = ss; }
    __syncthreads();
    if (tid < 32) {
        float S = red[tid], SS = red[32 + tid];
        #pragma unroll
        for (int off = 16; off; off >>= 1) {
            S  += __shfl_xor_sync(0xffffffffu, S, off);
            SS += __shfl_xor_sync(0xffffffffu, SS, off);
        }
        if (tid == 0) {
            float m = S / CV_;
            red[64] = m;
            red[65] = rsqrtf(SS / CV_ - m * m + 1e-5f);
        }
    }
    __syncthreads();
    float m = red[64], rs = red[65];

    const float* resp = (t >= GH_) ? (g_h[cur][t - GH_] + (o << 5) + vb) : nullptr;
    float* outp = g_h[cur ^ 1][t] + (o << 5) + vb;
    const float* w2 = ln2_w + (l * C_ + o) * V_ + vb;
    const float* b2 = ln2_b + (l * C_ + o) * V_ + vb;
    #pragma unroll
    for (int j = 0; j < 8; j++) {
        float r = 0.f;
        if (vb + j < V_) {
            float res = resp ? resp[j] : 0.f;
            r = fmaxf(fmaf((acc[j] - m) * rs, w2[j], b2[j]) + res, 0.f);
        }
        outp[j] = r;
    }
}

// ---------------- head: mean over V + linear ---------------------------------
__global__ void k_out(int cur,
                      const float* __restrict__ Wout,
                      const float* __restrict__ bout,
                      float* __restrict__ out) {
    __shared__ float pooled[C_];
    int t = blockIdx.x, tid = threadIdx.x;  // 256
    const float* h = g_h[cur][t];
    float s = 0.f;
    #pragma unroll
    for (int v = 0; v < V_; v++) s += h[(tid << 5) + v];
    pooled[tid] = s * (1.f / V_);
    __syncthreads();
    if (tid < NC_) {
        float a = bout[tid];
        #pragma unroll 8
        for (int c = 0; c < C_; c++) a = fmaf(Wout[tid * C_ + c], pooled[c], a);
        out[t * NC_ + tid] = a;
    }
}

// ---------------- launch ------------------------------------------------------
extern "C" void kernel_launch(void* const* d_in, const int* in_sizes, int n_in,
                              void* d_out, int out_size) {
    const float* x       = (const float*)d_in[0];
    const float* A       = (const float*)d_in[1];
    const float* ln_in_w = (const float*)d_in[2];
    const float* ln_in_b = (const float*)d_in[3];
    const float* W_in    = (const float*)d_in[4];
    const float* b_in    = (const float*)d_in[5];
    const float* Wg      = (const float*)d_in[6];
    const float* bg      = (const float*)d_in[7];
    const float* ln1_w   = (const float*)d_in[8];
    const float* ln1_b   = (const float*)d_in[9];
    const float* Wt      = (const float*)d_in[10];
    const float* bt      = (const float*)d_in[11];
    const float* ln2_w   = (const float*)d_in[12];
    const float* ln2_b   = (const float*)d_in[13];
    const float* imp     = (const float*)d_in[14];
    const float* W_out   = (const float*)d_in[15];
    const float* b_out   = (const float*)d_in[16];
    float* out = (float*)d_out;

    int gcn_smem = GCN_SMEM_FLOATS * (int)sizeof(float);
    cudaFuncSetAttribute(k_gcn, cudaFuncAttributeMaxDynamicSharedMemorySize, gcn_smem);

    {
        int n = L_ * K_ * C_ * C_;
        k_prep_wg<<<(n + 255) / 256, 256>>>(Wg);
    }
    {
        int n = L_ * C_ * C_;
        k_prep_wt<<<(n + 255) / 256, 256>>>(Wt);
    }
    {
        int n = L_ * CVP_;
        k_prep_aneg<<<(n + 255) / 256, 256>>>(ln1_b);
    }
    k_input<<<T_, 128>>>(x, ln_in_w, ln_in_b, W_in, b_in);

    int cur = 0;
    for (int l = 0; l < L_; l++) {
        k_gcn<<<T_, 1024, gcn_smem>>>(l, cur, A, imp, bg, ln1_w, ln1_b);
        k_tcn<<<T_, 1024>>>(l, cur, bt, ln2_w, ln2_b);
        cur ^= 1;
    }
    k_out<<<T_, 256>>>(cur, W_out, b_out, out);
}

// round 11
// speedup vs baseline: 1.8727x; 1.1018x over previous
#include <cuda_runtime.h>

#define L_   9
#define C_   256
#define K_   3
#define V_   25
#define VP_  32
#define G_   9
#define T_   128
#define NC_  60
#define CIN_ 3
#define GH_  4
#define CV_  (C_*V_)    /* 6400 */
#define CVP_ (C_*VP_)   /* 8192 */

// ---------------- scratch (device globals; zero-initialized at load) --------
__device__ __align__(16) float g_h[2][T_][CVP_];      // padded activations (pads stay 0)
__device__ __align__(16) float g_anorm[T_][CVP_];     // relu(LN1(z)), padded (pads stay 0)
__device__ __align__(16) float g_aneg[L_][CVP_];      // relu(LN1(zero frame)) per layer
__device__ __align__(16) float g_WgT[L_][K_][C_][C_]; // [l][k][ci][co]
__device__ __align__(16) float g_WtT[L_][G_][C_][C_]; // [l][g][ci][o]

// ---------------- weight prep (transpose) ------------------------------------
__global__ void k_prep_wg(const float* __restrict__ Wg) {
    int idx = blockIdx.x * blockDim.x + threadIdx.x;
    if (idx >= L_ * K_ * C_ * C_) return;
    int ci = idx % C_; int r = idx / C_;
    int co = r % C_;   r /= C_;
    int k  = r % K_;   int l = r / K_;
    g_WgT[l][k][ci][co] = Wg[((size_t)(l * K_ * C_ + k * C_ + co)) * C_ + ci];
}

__global__ void k_prep_wt(const float* __restrict__ Wt) {
    int idx = blockIdx.x * blockDim.x + threadIdx.x;
    if (idx >= L_ * C_ * C_) return;
    int c = idx % C_; int r = idx / C_;
    int o = r % C_;   int l = r / C_;
    const float* src = Wt + (((size_t)(l * C_ + o)) * C_ + c) * G_;  // 9 consecutive
    #pragma unroll
    for (int g = 0; g < G_; g++) g_WtT[l][g][c][o] = src[g];
}

__global__ void k_prep_aneg(const float* __restrict__ ln1_b) {
    int idx = blockIdx.x * blockDim.x + threadIdx.x;
    if (idx >= L_ * CVP_) return;
    int e = idx % CVP_, l = idx / CVP_;
    int c = e >> 5, v = e & 31;
    float r = 0.f;
    if (v < V_) r = fmaxf(ln1_b[(l * C_ + c) * V_ + v], 0.f);
    g_aneg[l][e] = r;
}

// ---------------- input: LN over (CIN,V) + 1x1 conv --------------------------
__global__ void k_input(const float* __restrict__ x,
                        const float* __restrict__ lnw,
                        const float* __restrict__ lnb,
                        const float* __restrict__ Win,
                        const float* __restrict__ bin) {
    __shared__ float hn[CIN_ * V_];
    __shared__ float red[16];
    int t = blockIdx.x, tid = threadIdx.x;  // 128 threads

    float xv = 0.f, s = 0.f, ss = 0.f;
    if (tid < CIN_ * V_) {
        int ci = tid / V_, v = tid % V_;
        xv = x[(size_t)ci * T_ * V_ + (size_t)t * V_ + v];
        s = xv; ss = xv * xv;
    }
    #pragma unroll
    for (int o = 16; o; o >>= 1) {
        s  += __shfl_xor_sync(0xffffffffu, s, o);
        ss += __shfl_xor_sync(0xffffffffu, ss, o);
    }
    int wid = tid >> 5, lane = tid & 31;
    if (lane == 0) { red[wid] = s; red[4 + wid] = ss; }
    __syncthreads();
    if (tid == 0) {
        float S = red[0] + red[1] + red[2] + red[3];
        float SS = red[4] + red[5] + red[6] + red[7];
        float m = S / (CIN_ * V_);
        red[8] = m;
        red[9] = rsqrtf(SS / (CIN_ * V_) - m * m + 1e-5f);
    }
    __syncthreads();
    float m = red[8], rs = red[9];
    if (tid < CIN_ * V_) hn[tid] = (xv - m) * rs * lnw[tid] + lnb[tid];
    __syncthreads();

    float* out = g_h[0][t];
    for (int e = tid; e < CVP_; e += 128) {
        int c = e >> 5, v = e & 31;
        float a = 0.f;
        if (v < V_) {
            a = bin[c];
            #pragma unroll
            for (int ci = 0; ci < CIN_; ci++)
                a = fmaf(Win[c * CIN_ + ci], hn[ci * V_ + v], a);
        }
        out[e] = a;
    }
}

// ---------------- GCN: z = sum_k (Wg_k h) A_k + LN1 + relu -------------------
#define GCN_SMEM_FLOATS (CVP_ + K_*CVP_ + K_*V_*V_ + K_*V_ + 66)
__global__ __launch_bounds__(1024, 1)
void k_gcn(int l, int cur,
           const float* __restrict__ A,
           const float* __restrict__ imp,
           const float* __restrict__ bg,
           const float* __restrict__ ln1_w,
           const float* __restrict__ ln1_b) {
    extern __shared__ __align__(16) float sm[];
    float* h_s  = sm;                          // 8192 (stride-32 padded)
    float* hA_s = sm + CVP_;                   // 24576: [k][c][wp32]
    float* Al_s = sm + CVP_ + K_*CVP_;         // 1875
    float* rsum = Al_s + K_*V_*V_;             // 75
    float* red  = rsum + K_*V_;                // 66

    int t = blockIdx.x, tid = threadIdx.x;     // 1024 threads
    {
        const float4* src = (const float4*)g_h[cur][t];
        float4* dst = (float4*)h_s;
        #pragma unroll
        for (int i = 0; i < 2; i++) dst[tid + i * 1024] = src[tid + i * 1024];
    }
    for (int i = tid; i < K_ * V_ * V_; i += 1024)
        Al_s[i] = A[i] * imp[l * K_ * V_ * V_ + i];
    __syncthreads();

    for (int i = tid; i < K_ * V_; i += 1024) {
        int k = i / V_, w = i % V_;
        float s = 0.f;
        #pragma unroll
        for (int v = 0; v < V_; v++) s += Al_s[k * V_ * V_ + v * V_ + w];
        rsum[i] = s;
    }
    // hA[k][c][w] = sum_v h[c][v] * Al[k][v][w]   (padded stride 32; pads never read)
    for (int e = tid; e < K_ * CV_; e += 1024) {
        int k = e / CV_, r = e % CV_, c = r / V_, w = r % V_;
        const float* hr = h_s + (c << 5);
        const float* ar = Al_s + k * V_ * V_ + w;
        float s = 0.f;
        #pragma unroll
        for (int v = 0; v < V_; v++) s = fmaf(hr[v], ar[v * V_], s);
        hA_s[k * CVP_ + (c << 5) + w] = s;
    }
    __syncthreads();

    // v-groups {8,8,8,1}: vg0-2 -> v in [vg*8, vg*8+8), vg3 -> v=24 only
    int c = tid & 255, vg = tid >> 8;
    float acc[8];
    float s = 0.f, ss = 0.f;
    float bg0 = bg[l * K_ * C_ + c];
    float bg1 = bg[l * K_ * C_ + C_ + c];
    float bg2 = bg[l * K_ * C_ + 2 * C_ + c];

    if (vg < 3) {
        int vb = vg << 3;
        #pragma unroll
        for (int j = 0; j < 8; j++) {
            int w = vb + j;
            acc[j] = bg0 * rsum[w] + bg1 * rsum[V_ + w] + bg2 * rsum[2 * V_ + w];
        }
        #pragma unroll
        for (int k = 0; k < K_; k++) {
            const float* wg = &g_WgT[l][k][0][c];
            const float* ap = hA_s + k * CVP_ + vb;
            #pragma unroll 4
            for (int ci = 0; ci < C_; ci++) {
                float wv = wg[ci * C_];
                float4 h0 = *(const float4*)(ap + (ci << 5));
                float4 h1 = *(const float4*)(ap + (ci << 5) + 4);
                acc[0] = fmaf(wv, h0.x, acc[0]);
                acc[1] = fmaf(wv, h0.y, acc[1]);
                acc[2] = fmaf(wv, h0.z, acc[2]);
                acc[3] = fmaf(wv, h0.w, acc[3]);
                acc[4] = fmaf(wv, h1.x, acc[4]);
                acc[5] = fmaf(wv, h1.y, acc[5]);
                acc[6] = fmaf(wv, h1.z, acc[6]);
                acc[7] = fmaf(wv, h1.w, acc[7]);
            }
        }
        #pragma unroll
        for (int j = 0; j < 8; j++) { s += acc[j]; ss += acc[j] * acc[j]; }
    } else {
        acc[0] = bg0 * rsum[24] + bg1 * rsum[V_ + 24] + bg2 * rsum[2 * V_ + 24];
        #pragma unroll
        for (int k = 0; k < K_; k++) {
            const float* wg = &g_WgT[l][k][0][c];
            const float* ap = hA_s + k * CVP_ + 24;
            #pragma unroll 4
            for (int ci = 0; ci < C_; ci++)
                acc[0] = fmaf(wg[ci * C_], ap[ci << 5], acc[0]);
        }
        s = acc[0]; ss = acc[0] * acc[0];
    }

    // block LN1 stats over (C,V)
    #pragma unroll
    for (int o = 16; o; o >>= 1) {
        s  += __shfl_xor_sync(0xffffffffu, s, o);
        ss += __shfl_xor_sync(0xffffffffu, ss, o);
    }
    int wid = tid >> 5, lane = tid & 31;
    if (lane == 0) { red[wid] = s; red[32 + wid] = ss; }
    __syncthreads();
    if (tid < 32) {
        float S = red[tid], SS = red[32 + tid];
        #pragma unroll
        for (int o = 16; o; o >>= 1) {
            S  += __shfl_xor_sync(0xffffffffu, S, o);
            SS += __shfl_xor_sync(0xffffffffu, SS, o);
        }
        if (tid == 0) {
            float m = S / CV_;
            red[64] = m;
            red[65] = rsqrtf(SS / CV_ - m * m + 1e-5f);
        }
    }
    __syncthreads();
    float m = red[64], rs = red[65];

    const float* w1 = ln1_w + (l * C_ + c) * V_;
    const float* b1 = ln1_b + (l * C_ + c) * V_;
    float* outp = g_anorm[t] + (c << 5);
    if (vg < 3) {
        int vb = vg << 3;
        #pragma unroll
        for (int j = 0; j < 8; j++) {
            int v = vb + j;
            outp[v] = fmaxf(fmaf((acc[j] - m) * rs, w1[v], b1[v]), 0.f);
        }
    } else {
        outp[24] = fmaxf(fmaf((acc[0] - m) * rs, w1[24], b1[24]), 0.f);
    }
}

// ---------------- TCN: temporal conv + LN2 + residual + relu -----------------
__global__ __launch_bounds__(1024, 1)
void k_tcn(int l, int cur,
           const float* __restrict__ bt,
           const float* __restrict__ ln2_w,
           const float* __restrict__ ln2_b) {
    __shared__ __align__(16) float a_s[CVP_];
    __shared__ float red[66];
    int t = blockIdx.x, tid = threadIdx.x;     // 1024 threads
    int o = tid & 255, vg = tid >> 8;
    int vb = vg << 3;                           // only meaningful for vg<3

    float acc[8];
    {
        float btv = bt[l * C_ + o];
        #pragma unroll
        for (int j = 0; j < 8; j++) acc[j] = btv;
    }

    for (int g = 0; g < G_; g++) {
        __syncthreads();
        int tau = t - g;
        const float4* src = (const float4*)((tau >= 0) ? g_anorm[tau] : g_aneg[l]);
        float4* dst = (float4*)a_s;
        #pragma unroll
        for (int i = 0; i < 2; i++) dst[tid + i * 1024] = src[tid + i * 1024];
        __syncthreads();

        const float* wt = &g_WtT[l][g][0][o];
        if (vg < 3) {
            const float* ap = a_s + vb;
            #pragma unroll 4
            for (int ci = 0; ci < C_; ci++) {
                float wv = wt[ci * C_];
                float4 a0 = *(const float4*)(ap + (ci << 5));
                float4 a1 = *(const float4*)(ap + (ci << 5) + 4);
                acc[0] = fmaf(wv, a0.x, acc[0]);
                acc[1] = fmaf(wv, a0.y, acc[1]);
                acc[2] = fmaf(wv, a0.z, acc[2]);
                acc[3] = fmaf(wv, a0.w, acc[3]);
                acc[4] = fmaf(wv, a1.x, acc[4]);
                acc[5] = fmaf(wv, a1.y, acc[5]);
                acc[6] = fmaf(wv, a1.z, acc[6]);
                acc[7] = fmaf(wv, a1.w, acc[7]);
            }
        } else {
            const float* ap = a_s + 24;
            #pragma unroll 4
            for (int ci = 0; ci < C_; ci++)
                acc[0] = fmaf(wt[ci * C_], ap[ci << 5], acc[0]);
        }
    }

    // LN2 stats over (C,V)
    float s = 0.f, ss = 0.f;
    if (vg < 3) {
        #pragma unroll
        for (int j = 0; j < 8; j++) { s += acc[j]; ss += acc[j] * acc[j]; }
    } else {
        s = acc[0]; ss = acc[0] * acc[0];
    }
    #pragma unroll
    for (int off = 16; off; off >>= 1) {
        s  += __shfl_xor_sync(0xffffffffu, s, off);
        ss += __shfl_xor_sync(0xffffffffu, ss, off);
    }
    int wid = tid >> 5, lane = tid & 31;
    if (lane == 0) { red[wid] = s; red[32 + wid] = ss; }
    __syncthreads();
    if (tid < 32) {
        float S = red[tid], SS = red[32 + tid];
        #pragma unroll
        for (int off = 16; off; off >>= 1) {
            S  += __shfl_xor_sync(0xffffffffu, S, off);
            SS += __shfl_xor_sync(0xffffffffu, SS, off);
        }
        if (tid == 0) {
            float m = S / CV_;
            red[64] = m;
            red[65] = rsqrtf(SS / CV_ - m * m + 1e-5f);
        }
    }
    __syncthreads();
    float m = red[64], rs = red[65];

    const float* resp = (t >= GH_) ? (g_h[cur][t - GH_] + (o << 5)) : nullptr;
    float* outp = g_h[cur ^ 1][t] + (o << 5);
    const float* w2 = ln2_w + (l * C_ + o) * V_;
    const float* b2 = ln2_b + (l * C_ + o) * V_;
    if (vg < 3) {
        #pragma unroll
        for (int j = 0; j < 8; j++) {
            int v = vb + j;
            float res = resp ? resp[v] : 0.f;
            outp[v] = fmaxf(fmaf((acc[j] - m) * rs, w2[v], b2[v]) + res, 0.f);
        }
    } else {
        float res = resp ? resp[24] : 0.f;
        outp[24] = fmaxf(fmaf((acc[0] - m) * rs, w2[24], b2[24]) + res, 0.f);
    }
}

// ---------------- head: mean over V + linear ---------------------------------
__global__ void k_out(int cur,
                      const float* __restrict__ Wout,
                      const float* __restrict__ bout,
                      float* __restrict__ out) {
    __shared__ float pooled[C_];
    int t = blockIdx.x, tid = threadIdx.x;  // 256
    const float* h = g_h[cur][t];
    float s = 0.f;
    #pragma unroll
    for (int v = 0; v < V_; v++) s += h[(tid << 5) + v];
    pooled[tid] = s * (1.f / V_);
    __syncthreads();
    if (tid < NC_) {
        float a = bout[tid];
        #pragma unroll 8
        for (int c = 0; c < C_; c++) a = fmaf(Wout[tid * C_ + c], pooled[c], a);
        out[t * NC_ + tid] = a;
    }
}

// ---------------- launch ------------------------------------------------------
extern "C" void kernel_launch(void* const* d_in, const int* in_sizes, int n_in,
                              void* d_out, int out_size) {
    const float* x       = (const float*)d_in[0];
    const float* A       = (const float*)d_in[1];
    const float* ln_in_w = (const float*)d_in[2];
    const float* ln_in_b = (const float*)d_in[3];
    const float* W_in    = (const float*)d_in[4];
    const float* b_in    = (const float*)d_in[5];
    const float* Wg      = (const float*)d_in[6];
    const float* bg      = (const float*)d_in[7];
    const float* ln1_w   = (const float*)d_in[8];
    const float* ln1_b   = (const float*)d_in[9];
    const float* Wt      = (const float*)d_in[10];
    const float* bt      = (const float*)d_in[11];
    const float* ln2_w   = (const float*)d_in[12];
    const float* ln2_b   = (const float*)d_in[13];
    const float* imp     = (const float*)d_in[14];
    const float* W_out   = (const float*)d_in[15];
    const float* b_out   = (const float*)d_in[16];
    float* out = (float*)d_out;

    int gcn_smem = GCN_SMEM_FLOATS * (int)sizeof(float);
    cudaFuncSetAttribute(k_gcn, cudaFuncAttributeMaxDynamicSharedMemorySize, gcn_smem);

    {
        int n = L_ * K_ * C_ * C_;
        k_prep_wg<<<(n + 255) / 256, 256>>>(Wg);
    }
    {
        int n = L_ * C_ * C_;
        k_prep_wt<<<(n + 255) / 256, 256>>>(Wt);
    }
    {
        int n = L_ * CVP_;
        k_prep_aneg<<<(n + 255) / 256, 256>>>(ln1_b);
    }
    k_input<<<T_, 128>>>(x, ln_in_w, ln_in_b, W_in, b_in);

    int cur = 0;
    for (int l = 0; l < L_; l++) {
        k_gcn<<<T_, 1024, gcn_smem>>>(l, cur, A, imp, bg, ln1_w, ln1_b);
        k_tcn<<<T_, 1024>>>(l, cur, bt, ln2_w, ln2_b);
        cur ^= 1;
    }
    k_out<<<T_, 256>>>(cur, W_out, b_out, out);
}